// round 1
// baseline (speedup 1.0000x reference)
#include <cuda_runtime.h>
#include <math.h>

#define T_SEQ 2048
#define HDIM  2048
#define NH    32
#define NKVH  8
#define HD    64
#define NTOK  4096   // B*T

// ---------------- scratch (no allocations allowed) ----------------
__device__ float  g_q[NTOK * HDIM];          // 4096 x 2048
__device__ float  g_k[NTOK * NKVH * HD];     // 4096 x 512
__device__ float  g_v[NTOK * NKVH * HD];     // 4096 x 512
__device__ float  g_attn[NTOK * HDIM];       // 4096 x 2048
__device__ float2 g_cs[T_SEQ * 32];          // cos/sin per (t, pair)

// ---------------- cos/sin table (double precision phases) ----------------
__global__ void cossin_kernel(float2* __restrict__ cs) {
    int idx = blockIdx.x * blockDim.x + threadIdx.x;   // T_SEQ*32 threads
    int t = idx >> 5;
    int i = idx & 31;
    double inv = pow(10000.0, -(double)(2 * i) / 64.0);
    double f = (double)t * inv;
    cs[idx] = make_float2((float)cos(f), (float)sin(f));
}

// ---------------- RoPE (in-place, buf layout [tok][nheads][64]) ----------------
__global__ void rope_kernel(float* __restrict__ buf, int nheads,
                            const float2* __restrict__ cs) {
    int idx = blockIdx.x * blockDim.x + threadIdx.x;
    int i   = idx & 31;
    int h   = (idx >> 5) % nheads;
    int tok = idx / (nheads * 32);
    int t   = tok & (T_SEQ - 1);
    float2 c = cs[(t << 5) + i];
    float* p = buf + ((size_t)tok * nheads + h) * HD + 2 * i;
    float re = p[0], im = p[1];
    p[0] = re * c.x - im * c.y;
    p[1] = re * c.y + im * c.x;
}

// ---------------- fp32 GEMM: C[M,N] = A[M,K] * B[K,N], tiles 128x128x16 ----------------
__global__ __launch_bounds__(256) void gemm_kernel(
    const float* __restrict__ A, const float* __restrict__ B,
    float* __restrict__ C, int M, int N, int K) {
    __shared__ float Ast[16][132];   // A tile transposed: [k][m]
    __shared__ float Bs[16][132];    // B tile: [k][n]

    const int tid = threadIdx.x;
    const int tr = tid >> 4;         // 0..15
    const int tc = tid & 15;         // 0..15
    const int brow = blockIdx.y * 128;
    const int bcol = blockIdx.x * 128;

    float acc[8][8];
#pragma unroll
    for (int i = 0; i < 8; i++)
#pragma unroll
        for (int j = 0; j < 8; j++) acc[i][j] = 0.f;

    const int ar  = tid >> 2;        // 0..63
    const int ac4 = (tid & 3) * 4;   // 0,4,8,12
    const int br  = tid >> 5;        // 0..7
    const int bc4 = (tid & 31) * 4;  // 0..124

    for (int k0 = 0; k0 < K; k0 += 16) {
#pragma unroll
        for (int hh = 0; hh < 2; hh++) {
            int r = ar + hh * 64;
            float4 v = *(const float4*)(A + (size_t)(brow + r) * K + k0 + ac4);
            Ast[ac4 + 0][r] = v.x; Ast[ac4 + 1][r] = v.y;
            Ast[ac4 + 2][r] = v.z; Ast[ac4 + 3][r] = v.w;
        }
#pragma unroll
        for (int hh = 0; hh < 2; hh++) {
            int r = br + hh * 8;
            float4 v = *(const float4*)(B + (size_t)(k0 + r) * N + bcol + bc4);
            *(float4*)&Bs[r][bc4] = v;
        }
        __syncthreads();
#pragma unroll
        for (int kk = 0; kk < 16; kk++) {
            float a[8], bb[8];
            *(float4*)&a[0]  = *(const float4*)&Ast[kk][tr * 4];
            *(float4*)&a[4]  = *(const float4*)&Ast[kk][tr * 4 + 64];
            *(float4*)&bb[0] = *(const float4*)&Bs[kk][tc * 4];
            *(float4*)&bb[4] = *(const float4*)&Bs[kk][tc * 4 + 64];
#pragma unroll
            for (int i = 0; i < 8; i++)
#pragma unroll
                for (int j = 0; j < 8; j++) acc[i][j] += a[i] * bb[j];
        }
        __syncthreads();
    }

#pragma unroll
    for (int ih = 0; ih < 2; ih++)
#pragma unroll
        for (int ii = 0; ii < 4; ii++) {
            size_t row = (size_t)brow + tr * 4 + ii + ih * 64;
            float* Cp = C + row * N + bcol + tc * 4;
            int ai = ih * 4 + ii;
            *(float4*)(Cp)      = make_float4(acc[ai][0], acc[ai][1], acc[ai][2], acc[ai][3]);
            *(float4*)(Cp + 64) = make_float4(acc[ai][4], acc[ai][5], acc[ai][6], acc[ai][7]);
        }
}

// ---------------- causal flash attention, fp32, 64x64 tiles ----------------
// Q: [tok][32*64] (scaled on load), K/V: [tok][8*64], O: [tok][32*64]
__global__ __launch_bounds__(256) void flash_kernel(
    const float* __restrict__ Q, const float* __restrict__ K,
    const float* __restrict__ V, float* __restrict__ O) {
    extern __shared__ float sm[];
    float (*Qt)[68] = (float(*)[68])(sm);                 // [d][i] transposed
    float (*Kt)[68] = (float(*)[68])(sm + 64 * 68);       // [d][j] transposed
    float (*Vs)[68] = (float(*)[68])(sm + 2 * 64 * 68);   // [j][d]
    float (*Pt)[68] = (float(*)[68])(sm + 3 * 64 * 68);   // [j][i] transposed

    const int tid = threadIdx.x;
    const int tr = tid >> 4;      // row group: rows tr*4..tr*4+3
    const int tc = tid & 15;      // col group
    const int qtile = blockIdx.x;
    const int h = blockIdx.y;
    const int b = blockIdx.z;
    const int kvh = h >> 2;       // groups = 4
    const size_t qtok0 = (size_t)b * T_SEQ + qtile * 64;

    const int lrow = tid >> 2;    // 0..63
    const int lc4  = tid & 3;

    // load Q tile (transposed, pre-scaled by 1/sqrt(64))
#pragma unroll
    for (int rep = 0; rep < 4; rep++) {
        int c4 = lc4 + rep * 4;
        float4 v = *(const float4*)(Q + (qtok0 + lrow) * HDIM + h * HD + c4 * 4);
        Qt[c4 * 4 + 0][lrow] = v.x * 0.125f;
        Qt[c4 * 4 + 1][lrow] = v.y * 0.125f;
        Qt[c4 * 4 + 2][lrow] = v.z * 0.125f;
        Qt[c4 * 4 + 3][lrow] = v.w * 0.125f;
    }

    float m[4], l[4], o[4][4];
#pragma unroll
    for (int i = 0; i < 4; i++) {
        m[i] = -1e30f; l[i] = 0.f;
#pragma unroll
        for (int j = 0; j < 4; j++) o[i][j] = 0.f;
    }
    __syncthreads();

    for (int kt = 0; kt <= qtile; kt++) {
        const size_t ktok0 = (size_t)b * T_SEQ + kt * 64;
#pragma unroll
        for (int rep = 0; rep < 4; rep++) {
            int c4 = lc4 + rep * 4;
            float4 kv = *(const float4*)(K + (ktok0 + lrow) * (NKVH * HD) + kvh * HD + c4 * 4);
            Kt[c4 * 4 + 0][lrow] = kv.x; Kt[c4 * 4 + 1][lrow] = kv.y;
            Kt[c4 * 4 + 2][lrow] = kv.z; Kt[c4 * 4 + 3][lrow] = kv.w;
            float4 vv = *(const float4*)(V + (ktok0 + lrow) * (NKVH * HD) + kvh * HD + c4 * 4);
            *(float4*)&Vs[lrow][c4 * 4] = vv;
        }
        __syncthreads();

        // S = Q K^T
        float s[4][4];
#pragma unroll
        for (int i = 0; i < 4; i++)
#pragma unroll
            for (int j = 0; j < 4; j++) s[i][j] = 0.f;
#pragma unroll 8
        for (int d = 0; d < 64; d++) {
            float4 a4 = *(const float4*)&Qt[d][tr * 4];
            float4 b4 = *(const float4*)&Kt[d][tc * 4];
            float a[4]  = {a4.x, a4.y, a4.z, a4.w};
            float bb[4] = {b4.x, b4.y, b4.z, b4.w};
#pragma unroll
            for (int i = 0; i < 4; i++)
#pragma unroll
                for (int j = 0; j < 4; j++) s[i][j] += a[i] * bb[j];
        }
        if (kt == qtile) {
#pragma unroll
            for (int i = 0; i < 4; i++) {
                int qi = tr * 4 + i;
#pragma unroll
                for (int j = 0; j < 4; j++)
                    if (tc * 4 + j > qi) s[i][j] = -1e30f;
            }
        }

        // online softmax; rows are owned by 16 consecutive lanes (half-warp)
#pragma unroll
        for (int i = 0; i < 4; i++) {
            float mx = fmaxf(fmaxf(s[i][0], s[i][1]), fmaxf(s[i][2], s[i][3]));
#pragma unroll
            for (int off = 8; off >= 1; off >>= 1)
                mx = fmaxf(mx, __shfl_xor_sync(0xffffffffu, mx, off));
            float mn = fmaxf(m[i], mx);
            float fac = __expf(m[i] - mn);
            m[i] = mn;
            float rs = 0.f;
#pragma unroll
            for (int j = 0; j < 4; j++) {
                float p = __expf(s[i][j] - mn);
                s[i][j] = p;
                rs += p;
            }
#pragma unroll
            for (int off = 8; off >= 1; off >>= 1)
                rs += __shfl_xor_sync(0xffffffffu, rs, off);
            l[i] = l[i] * fac + rs;
#pragma unroll
            for (int j = 0; j < 4; j++) o[i][j] *= fac;
#pragma unroll
            for (int j = 0; j < 4; j++) Pt[tc * 4 + j][tr * 4 + i] = s[i][j];
        }
        __syncthreads();

        // O += P V
#pragma unroll 8
        for (int j = 0; j < 64; j++) {
            float4 p4 = *(const float4*)&Pt[j][tr * 4];
            float4 v4 = *(const float4*)&Vs[j][tc * 4];
            float pp[4] = {p4.x, p4.y, p4.z, p4.w};
            float vv[4] = {v4.x, v4.y, v4.z, v4.w};
#pragma unroll
            for (int i = 0; i < 4; i++)
#pragma unroll
                for (int jj = 0; jj < 4; jj++) o[i][jj] += pp[i] * vv[jj];
        }
        __syncthreads();
    }

#pragma unroll
    for (int i = 0; i < 4; i++) {
        float inv = 1.0f / l[i];
        float4 v = make_float4(o[i][0] * inv, o[i][1] * inv, o[i][2] * inv, o[i][3] * inv);
        *(float4*)(O + (qtok0 + tr * 4 + i) * HDIM + h * HD + tc * 4) = v;
    }
}

// ---------------- launch ----------------
extern "C" void kernel_launch(void* const* d_in, const int* in_sizes, int n_in,
                              void* d_out, int out_size) {
    const float* x  = (const float*)d_in[0];
    const float* wq = (const float*)d_in[1];
    const float* wk = (const float*)d_in[2];
    const float* wv = (const float*)d_in[3];
    const float* wo = (const float*)d_in[4];
    float* out = (float*)d_out;

    float *q, *k, *v, *attn;
    float2* cs;
    cudaGetSymbolAddress((void**)&q,    g_q);
    cudaGetSymbolAddress((void**)&k,    g_k);
    cudaGetSymbolAddress((void**)&v,    g_v);
    cudaGetSymbolAddress((void**)&attn, g_attn);
    cudaGetSymbolAddress((void**)&cs,   g_cs);

    const int flash_smem = 4 * 64 * 68 * 4;  // 69632 bytes
    cudaFuncSetAttribute(flash_kernel, cudaFuncAttributeMaxDynamicSharedMemorySize, flash_smem);

    cossin_kernel<<<(T_SEQ * 32) / 256, 256>>>(cs);

    gemm_kernel<<<dim3(16, 32), 256>>>(x, wq, q, NTOK, HDIM, HDIM);
    gemm_kernel<<<dim3(4, 32), 256>>>(x, wk, k, NTOK, NKVH * HD, HDIM);
    gemm_kernel<<<dim3(4, 32), 256>>>(x, wv, v, NTOK, NKVH * HD, HDIM);

    rope_kernel<<<(NTOK * NH * 32) / 256, 256>>>(q, NH, cs);
    rope_kernel<<<(NTOK * NKVH * 32) / 256, 256>>>(k, NKVH, cs);

    flash_kernel<<<dim3(T_SEQ / 64, NH, 2), 256, flash_smem>>>(q, k, v, attn);

    gemm_kernel<<<dim3(16, 32), 256>>>(attn, wo, out, NTOK, HDIM, HDIM);
}

// round 2
// speedup vs baseline: 1.6372x; 1.6372x over previous
#include <cuda_runtime.h>
#include <math.h>
#include <stdint.h>

#define T_SEQ 2048
#define HDIM  2048
#define NH    32
#define NKVH  8
#define HD    64
#define NTOK  4096   // B*T

// ---------------- GEMM tile params ----------------
#define BM 128
#define BN 256
#define BK 32
#define PA 36                       // A row pitch (floats), 144B (16B aligned, conflict-free ldmatrix)
#define PB 264                      // B row pitch (floats), bank = 8k+n -> conflict-free frag loads
#define AS_FLOATS (BM*PA)           // 4608
#define BS_FLOATS (BK*PB)           // 8448
#define STAGE_FLOATS (AS_FLOATS + BS_FLOATS)  // 13056 floats = 52224 B
#define GEMM_SMEM (2*STAGE_FLOATS*4)          // 104448 B

// ---------------- scratch (no allocations allowed) ----------------
__device__ float  g_q[NTOK * HDIM];
__device__ float  g_k[NTOK * NKVH * HD];
__device__ float  g_v[NTOK * NKVH * HD];
__device__ float  g_attn[NTOK * HDIM];
__device__ float2 g_cs[T_SEQ * 32];

// ---------------- cos/sin table ----------------
__global__ void cossin_kernel(float2* __restrict__ cs) {
    int idx = blockIdx.x * blockDim.x + threadIdx.x;
    int t = idx >> 5;
    int i = idx & 31;
    double inv = pow(10000.0, -(double)(2 * i) / 64.0);
    double f = (double)t * inv;
    cs[idx] = make_float2((float)cos(f), (float)sin(f));
}

// ---------------- RoPE ----------------
__global__ void rope_kernel(float* __restrict__ buf, int nheads,
                            const float2* __restrict__ cs) {
    int idx = blockIdx.x * blockDim.x + threadIdx.x;
    int i   = idx & 31;
    int h   = (idx >> 5) % nheads;
    int tok = idx / (nheads * 32);
    int t   = tok & (T_SEQ - 1);
    float2 c = cs[(t << 5) + i];
    float* p = buf + ((size_t)tok * nheads + h) * HD + 2 * i;
    float re = p[0], im = p[1];
    p[0] = re * c.x - im * c.y;
    p[1] = re * c.y + im * c.x;
}

// ---------------- tf32 tensor-core GEMM ----------------
__device__ __forceinline__ void cp16(float* s, const float* g) {
    uint32_t sa = (uint32_t)__cvta_generic_to_shared(s);
    asm volatile("cp.async.cg.shared.global [%0], [%1], 16;" :: "r"(sa), "l"(g));
}
__device__ __forceinline__ void cp_commit() { asm volatile("cp.async.commit_group;"); }
__device__ __forceinline__ void cp_wait1()  { asm volatile("cp.async.wait_group 1;"); }

__device__ __forceinline__ uint32_t f2tf(float f) {
    uint32_t r;
    asm("cvt.rna.tf32.f32 %0, %1;" : "=r"(r) : "f"(f));
    return r;
}

__global__ __launch_bounds__(256, 1) void gemm_tf32(
    const float* __restrict__ A, const float* __restrict__ B,
    float* __restrict__ C, int M, int N, int K)
{
    extern __shared__ float sm[];
    const int tid  = threadIdx.x;
    const int lane = tid & 31;
    const int w    = tid >> 5;
    const int wm   = w >> 2;     // 0..1 (M)
    const int wn   = w & 3;      // 0..3 (N)
    const int brow = blockIdx.y * BM;
    const int bcol = blockIdx.x * BN;

    float acc[4][8][4];
#pragma unroll
    for (int mt = 0; mt < 4; mt++)
#pragma unroll
        for (int nt = 0; nt < 8; nt++)
#pragma unroll
            for (int i = 0; i < 4; i++) acc[mt][nt][i] = 0.f;

    auto load_stage = [&](int s, int k0) {
        float* As = sm + s * STAGE_FLOATS;
        float* Bs = As + AS_FLOATS;
        const int kq = tid & 7;
        const int mbase = tid >> 3;        // 0..31
#pragma unroll
        for (int r = 0; r < 4; r++) {
            int m = mbase + 32 * r;
            cp16(&As[m * PA + 4 * kq], A + (size_t)(brow + m) * K + k0 + 4 * kq);
        }
#pragma unroll
        for (int r = 0; r < 4; r++) {
            int k = w + 8 * r;
#pragma unroll
            for (int c = 0; c < 2; c++) {
                int n = 4 * lane + 128 * c;
                cp16(&Bs[k * PB + n], B + (size_t)(k0 + k) * N + bcol + n);
            }
        }
    };

    const int ntk = K / BK;
    load_stage(0, 0);   cp_commit();
    load_stage(1, BK);  cp_commit();

    const int aRow    = lane & 15;          // ldmatrix row within m-tile
    const int aColSel = (lane >> 4) * 4;    // 0 or 4 (k granule)
    const int tig     = lane & 3;
    const int g       = lane >> 2;

    for (int t = 0; t < ntk; t++) {
        cp_wait1();
        __syncthreads();
        float* As = sm + (t & 1) * STAGE_FLOATS;
        float* Bs = As + AS_FLOATS;

#pragma unroll
        for (int ks = 0; ks < 4; ks++) {
            uint32_t a[4][4];
#pragma unroll
            for (int mt = 0; mt < 4; mt++) {
                float* p = &As[(wm * 64 + mt * 16 + aRow) * PA + ks * 8 + aColSel];
                uint32_t sa = (uint32_t)__cvta_generic_to_shared(p);
                uint32_t r0, r1, r2, r3;
                asm volatile("ldmatrix.sync.aligned.m8n8.x4.shared.b16 {%0,%1,%2,%3}, [%4];"
                             : "=r"(r0), "=r"(r1), "=r"(r2), "=r"(r3) : "r"(sa));
                a[mt][0] = f2tf(__uint_as_float(r0));
                a[mt][1] = f2tf(__uint_as_float(r1));
                a[mt][2] = f2tf(__uint_as_float(r2));
                a[mt][3] = f2tf(__uint_as_float(r3));
            }
#pragma unroll
            for (int nt = 0; nt < 8; nt++) {
                int n = wn * 64 + nt * 8 + g;
                uint32_t b0 = f2tf(Bs[(ks * 8 + tig) * PB + n]);
                uint32_t b1 = f2tf(Bs[(ks * 8 + 4 + tig) * PB + n]);
#pragma unroll
                for (int mt = 0; mt < 4; mt++) {
                    asm volatile(
                        "mma.sync.aligned.m16n8k8.row.col.f32.tf32.tf32.f32 "
                        "{%0,%1,%2,%3}, {%4,%5,%6,%7}, {%8,%9}, {%0,%1,%2,%3};"
                        : "+f"(acc[mt][nt][0]), "+f"(acc[mt][nt][1]),
                          "+f"(acc[mt][nt][2]), "+f"(acc[mt][nt][3])
                        : "r"(a[mt][0]), "r"(a[mt][1]), "r"(a[mt][2]), "r"(a[mt][3]),
                          "r"(b0), "r"(b1));
                }
            }
        }
        __syncthreads();
        if (t + 2 < ntk) load_stage(t & 1, (t + 2) * BK);
        cp_commit();
    }

    // epilogue: c0,c1 = (g, 2tig..), c2,c3 = (g+8, 2tig..)
#pragma unroll
    for (int mt = 0; mt < 4; mt++) {
        int row = brow + wm * 64 + mt * 16 + g;
#pragma unroll
        for (int nt = 0; nt < 8; nt++) {
            int col = bcol + wn * 64 + nt * 8 + 2 * tig;
            *(float2*)&C[(size_t)row * N + col]       = make_float2(acc[mt][nt][0], acc[mt][nt][1]);
            *(float2*)&C[(size_t)(row + 8) * N + col] = make_float2(acc[mt][nt][2], acc[mt][nt][3]);
        }
    }
}

// ---------------- causal flash attention, fp32, 64x64 tiles ----------------
__global__ __launch_bounds__(256) void flash_kernel(
    const float* __restrict__ Q, const float* __restrict__ K,
    const float* __restrict__ V, float* __restrict__ O) {
    extern __shared__ float sm[];
    float (*Qt)[68] = (float(*)[68])(sm);
    float (*Kt)[68] = (float(*)[68])(sm + 64 * 68);
    float (*Vs)[68] = (float(*)[68])(sm + 2 * 64 * 68);
    float (*Pt)[68] = (float(*)[68])(sm + 3 * 64 * 68);

    const int tid = threadIdx.x;
    const int tr = tid >> 4;
    const int tc = tid & 15;
    const int qtile = blockIdx.x;
    const int h = blockIdx.y;
    const int b = blockIdx.z;
    const int kvh = h >> 2;
    const size_t qtok0 = (size_t)b * T_SEQ + qtile * 64;

    const int lrow = tid >> 2;
    const int lc4  = tid & 3;

#pragma unroll
    for (int rep = 0; rep < 4; rep++) {
        int c4 = lc4 + rep * 4;
        float4 v = *(const float4*)(Q + (qtok0 + lrow) * HDIM + h * HD + c4 * 4);
        Qt[c4 * 4 + 0][lrow] = v.x * 0.125f;
        Qt[c4 * 4 + 1][lrow] = v.y * 0.125f;
        Qt[c4 * 4 + 2][lrow] = v.z * 0.125f;
        Qt[c4 * 4 + 3][lrow] = v.w * 0.125f;
    }

    float m[4], l[4], o[4][4];
#pragma unroll
    for (int i = 0; i < 4; i++) {
        m[i] = -1e30f; l[i] = 0.f;
#pragma unroll
        for (int j = 0; j < 4; j++) o[i][j] = 0.f;
    }
    __syncthreads();

    for (int kt = 0; kt <= qtile; kt++) {
        const size_t ktok0 = (size_t)b * T_SEQ + kt * 64;
#pragma unroll
        for (int rep = 0; rep < 4; rep++) {
            int c4 = lc4 + rep * 4;
            float4 kv = *(const float4*)(K + (ktok0 + lrow) * (NKVH * HD) + kvh * HD + c4 * 4);
            Kt[c4 * 4 + 0][lrow] = kv.x; Kt[c4 * 4 + 1][lrow] = kv.y;
            Kt[c4 * 4 + 2][lrow] = kv.z; Kt[c4 * 4 + 3][lrow] = kv.w;
            float4 vv = *(const float4*)(V + (ktok0 + lrow) * (NKVH * HD) + kvh * HD + c4 * 4);
            *(float4*)&Vs[lrow][c4 * 4] = vv;
        }
        __syncthreads();

        float s[4][4];
#pragma unroll
        for (int i = 0; i < 4; i++)
#pragma unroll
            for (int j = 0; j < 4; j++) s[i][j] = 0.f;
#pragma unroll 8
        for (int d = 0; d < 64; d++) {
            float4 a4 = *(const float4*)&Qt[d][tr * 4];
            float4 b4 = *(const float4*)&Kt[d][tc * 4];
            float a[4]  = {a4.x, a4.y, a4.z, a4.w};
            float bb[4] = {b4.x, b4.y, b4.z, b4.w};
#pragma unroll
            for (int i = 0; i < 4; i++)
#pragma unroll
                for (int j = 0; j < 4; j++) s[i][j] += a[i] * bb[j];
        }
        if (kt == qtile) {
#pragma unroll
            for (int i = 0; i < 4; i++) {
                int qi = tr * 4 + i;
#pragma unroll
                for (int j = 0; j < 4; j++)
                    if (tc * 4 + j > qi) s[i][j] = -1e30f;
            }
        }

#pragma unroll
        for (int i = 0; i < 4; i++) {
            float mx = fmaxf(fmaxf(s[i][0], s[i][1]), fmaxf(s[i][2], s[i][3]));
#pragma unroll
            for (int off = 8; off >= 1; off >>= 1)
                mx = fmaxf(mx, __shfl_xor_sync(0xffffffffu, mx, off));
            float mn = fmaxf(m[i], mx);
            float fac = __expf(m[i] - mn);
            m[i] = mn;
            float rs = 0.f;
#pragma unroll
            for (int j = 0; j < 4; j++) {
                float p = __expf(s[i][j] - mn);
                s[i][j] = p;
                rs += p;
            }
#pragma unroll
            for (int off = 8; off >= 1; off >>= 1)
                rs += __shfl_xor_sync(0xffffffffu, rs, off);
            l[i] = l[i] * fac + rs;
#pragma unroll
            for (int j = 0; j < 4; j++) o[i][j] *= fac;
#pragma unroll
            for (int j = 0; j < 4; j++) Pt[tc * 4 + j][tr * 4 + i] = s[i][j];
        }
        __syncthreads();

#pragma unroll 8
        for (int j = 0; j < 64; j++) {
            float4 p4 = *(const float4*)&Pt[j][tr * 4];
            float4 v4 = *(const float4*)&Vs[j][tc * 4];
            float pp[4] = {p4.x, p4.y, p4.z, p4.w};
            float vv[4] = {v4.x, v4.y, v4.z, v4.w};
#pragma unroll
            for (int i = 0; i < 4; i++)
#pragma unroll
                for (int jj = 0; jj < 4; jj++) o[i][jj] += pp[i] * vv[jj];
        }
        __syncthreads();
    }

#pragma unroll
    for (int i = 0; i < 4; i++) {
        float inv = 1.0f / l[i];
        float4 v = make_float4(o[i][0] * inv, o[i][1] * inv, o[i][2] * inv, o[i][3] * inv);
        *(float4*)(O + (qtok0 + tr * 4 + i) * HDIM + h * HD + tc * 4) = v;
    }
}

// ---------------- launch ----------------
extern "C" void kernel_launch(void* const* d_in, const int* in_sizes, int n_in,
                              void* d_out, int out_size) {
    const float* x  = (const float*)d_in[0];
    const float* wq = (const float*)d_in[1];
    const float* wk = (const float*)d_in[2];
    const float* wv = (const float*)d_in[3];
    const float* wo = (const float*)d_in[4];
    float* out = (float*)d_out;

    float *q, *k, *v, *attn;
    float2* cs;
    cudaGetSymbolAddress((void**)&q,    g_q);
    cudaGetSymbolAddress((void**)&k,    g_k);
    cudaGetSymbolAddress((void**)&v,    g_v);
    cudaGetSymbolAddress((void**)&attn, g_attn);
    cudaGetSymbolAddress((void**)&cs,   g_cs);

    const int flash_smem = 4 * 64 * 68 * 4;
    cudaFuncSetAttribute(flash_kernel, cudaFuncAttributeMaxDynamicSharedMemorySize, flash_smem);
    cudaFuncSetAttribute(gemm_tf32, cudaFuncAttributeMaxDynamicSharedMemorySize, GEMM_SMEM);

    cossin_kernel<<<(T_SEQ * 32) / 256, 256>>>(cs);

    gemm_tf32<<<dim3(HDIM / BN, NTOK / BM), 256, GEMM_SMEM>>>(x, wq, q, NTOK, HDIM, HDIM);
    gemm_tf32<<<dim3((NKVH * HD) / BN, NTOK / BM), 256, GEMM_SMEM>>>(x, wk, k, NTOK, NKVH * HD, HDIM);
    gemm_tf32<<<dim3((NKVH * HD) / BN, NTOK / BM), 256, GEMM_SMEM>>>(x, wv, v, NTOK, NKVH * HD, HDIM);

    rope_kernel<<<(NTOK * NH * 32) / 256, 256>>>(q, NH, cs);
    rope_kernel<<<(NTOK * NKVH * 32) / 256, 256>>>(k, NKVH, cs);

    flash_kernel<<<dim3(T_SEQ / 64, NH, 2), 256, flash_smem>>>(q, k, v, attn);

    gemm_tf32<<<dim3(HDIM / BN, NTOK / BM), 256, GEMM_SMEM>>>(attn, wo, out, NTOK, HDIM, HDIM);
}

// round 3
// speedup vs baseline: 2.6594x; 1.6244x over previous
#include <cuda_runtime.h>
#include <math.h>
#include <stdint.h>

#define T_SEQ 2048
#define HDIM  2048
#define NH    32
#define NKVH  8
#define HD    64
#define NTOK  4096
#define KVDIM (NKVH*HD)

// ---------------- GEMM tile params ----------------
#define BM 128
#define BN 256
#define BK 32
#define PA 36
#define PB 264
#define AS_FLOATS (BM*PA)
#define BS_FLOATS (BK*PB)
#define STAGE_FLOATS (AS_FLOATS + BS_FLOATS)
#define GEMM_SMEM (2*STAGE_FLOATS*4)

// ---------------- flash params ----------------
#define FQ 128            // q rows / CTA
#define FK 64             // kv tokens / tile
#define FP 72             // smem pitch (floats): conflict-free A and B frag LDS
#define FLASH_SMEM ((FQ*FP + FQ*FP + FK*FP)*4)   // Qs + (K|P) + Vs = 92160 B

// ---------------- scratch ----------------
__device__ float  g_q[NTOK * HDIM];
__device__ float  g_k[NTOK * KVDIM];
__device__ float  g_v[NTOK * KVDIM];
__device__ float  g_attn[NTOK * HDIM];
__device__ float2 g_cs[T_SEQ * 32];

// ---------------- cos/sin ----------------
__global__ void cossin_kernel(float2* __restrict__ cs) {
    int idx = blockIdx.x * blockDim.x + threadIdx.x;
    int t = idx >> 5;
    int i = idx & 31;
    double inv = pow(10000.0, -(double)(2 * i) / 64.0);
    double f = (double)t * inv;
    cs[idx] = make_float2((float)cos(f), (float)sin(f));
}

// ---------------- helpers ----------------
__device__ __forceinline__ void cp16(float* s, const float* g) {
    uint32_t sa = (uint32_t)__cvta_generic_to_shared(s);
    asm volatile("cp.async.cg.shared.global [%0], [%1], 16;" :: "r"(sa), "l"(g));
}
__device__ __forceinline__ void cp_commit() { asm volatile("cp.async.commit_group;"); }
__device__ __forceinline__ void cp_wait1()  { asm volatile("cp.async.wait_group 1;"); }
__device__ __forceinline__ uint32_t f2tf(float f) {
    uint32_t r;
    asm("cvt.rna.tf32.f32 %0, %1;" : "=r"(r) : "f"(f));
    return r;
}
__device__ __forceinline__ void mma_tf32(float* c, const uint32_t* a, uint32_t b0, uint32_t b1) {
    asm volatile(
        "mma.sync.aligned.m16n8k8.row.col.f32.tf32.tf32.f32 "
        "{%0,%1,%2,%3}, {%4,%5,%6,%7}, {%8,%9}, {%0,%1,%2,%3};"
        : "+f"(c[0]), "+f"(c[1]), "+f"(c[2]), "+f"(c[3])
        : "r"(a[0]), "r"(a[1]), "r"(a[2]), "r"(a[3]), "r"(b0), "r"(b1));
}

// ---------------- fused QKV GEMM (tf32) with RoPE epilogue ----------------
// grid.x: 0..7 -> wq (N=2048), 8..9 -> wk (N=512), 10..11 -> wv (N=512)
__global__ __launch_bounds__(256, 1) void gemm_qkv(
    const float* __restrict__ A,
    const float* __restrict__ wq, const float* __restrict__ wk, const float* __restrict__ wv,
    float* __restrict__ q, float* __restrict__ k, float* __restrict__ v,
    const float2* __restrict__ cs)
{
    extern __shared__ float sm[];
    const int bx = blockIdx.x;
    int sec, bcol, N;
    const float *B; float *C; bool rope;
    if (bx < 8)       { sec = 0; bcol = bx * BN;        N = HDIM;  B = wq; C = q; rope = true;  }
    else if (bx < 10) { sec = 1; bcol = (bx - 8) * BN;  N = KVDIM; B = wk; C = k; rope = true;  }
    else              { sec = 2; bcol = (bx - 10) * BN; N = KVDIM; B = wv; C = v; rope = false; }
    (void)sec;
    const int K = HDIM;

    const int tid  = threadIdx.x;
    const int lane = tid & 31;
    const int w    = tid >> 5;
    const int wm   = w >> 2;
    const int wn   = w & 3;
    const int brow = blockIdx.y * BM;

    float acc[4][8][4];
#pragma unroll
    for (int mt = 0; mt < 4; mt++)
#pragma unroll
        for (int nt = 0; nt < 8; nt++)
#pragma unroll
            for (int i = 0; i < 4; i++) acc[mt][nt][i] = 0.f;

    auto load_stage = [&](int s, int k0) {
        float* As = sm + s * STAGE_FLOATS;
        float* Bs = As + AS_FLOATS;
        const int kq = tid & 7;
        const int mbase = tid >> 3;
#pragma unroll
        for (int r = 0; r < 4; r++) {
            int m = mbase + 32 * r;
            cp16(&As[m * PA + 4 * kq], A + (size_t)(brow + m) * K + k0 + 4 * kq);
        }
#pragma unroll
        for (int r = 0; r < 4; r++) {
            int kk = w + 8 * r;
#pragma unroll
            for (int c = 0; c < 2; c++) {
                int n = 4 * lane + 128 * c;
                cp16(&Bs[kk * PB + n], B + (size_t)(k0 + kk) * N + bcol + n);
            }
        }
    };

    const int ntk = K / BK;
    load_stage(0, 0);   cp_commit();
    load_stage(1, BK);  cp_commit();

    const int aRow    = lane & 15;
    const int aColSel = (lane >> 4) * 4;
    const int tig     = lane & 3;
    const int g       = lane >> 2;

    for (int t = 0; t < ntk; t++) {
        cp_wait1();
        __syncthreads();
        float* As = sm + (t & 1) * STAGE_FLOATS;
        float* Bs = As + AS_FLOATS;
#pragma unroll
        for (int ks = 0; ks < 4; ks++) {
            uint32_t a[4][4];
#pragma unroll
            for (int mt = 0; mt < 4; mt++) {
                float* p = &As[(wm * 64 + mt * 16 + aRow) * PA + ks * 8 + aColSel];
                uint32_t sa = (uint32_t)__cvta_generic_to_shared(p);
                uint32_t r0, r1, r2, r3;
                asm volatile("ldmatrix.sync.aligned.m8n8.x4.shared.b16 {%0,%1,%2,%3}, [%4];"
                             : "=r"(r0), "=r"(r1), "=r"(r2), "=r"(r3) : "r"(sa));
                a[mt][0] = f2tf(__uint_as_float(r0));
                a[mt][1] = f2tf(__uint_as_float(r1));
                a[mt][2] = f2tf(__uint_as_float(r2));
                a[mt][3] = f2tf(__uint_as_float(r3));
            }
#pragma unroll
            for (int nt = 0; nt < 8; nt++) {
                int n = wn * 64 + nt * 8 + g;
                uint32_t b0 = f2tf(Bs[(ks * 8 + tig) * PB + n]);
                uint32_t b1 = f2tf(Bs[(ks * 8 + 4 + tig) * PB + n]);
#pragma unroll
                for (int mt = 0; mt < 4; mt++)
                    mma_tf32(acc[mt][nt], a[mt], b0, b1);
            }
        }
        __syncthreads();
        if (t + 2 < ntk) load_stage(t & 1, (t + 2) * BK);
        cp_commit();
    }

#pragma unroll
    for (int mt = 0; mt < 4; mt++) {
        int row0 = brow + wm * 64 + mt * 16 + g;
#pragma unroll
        for (int nt = 0; nt < 8; nt++) {
            int col = bcol + wn * 64 + nt * 8 + 2 * tig;
#pragma unroll
            for (int hh = 0; hh < 2; hh++) {
                int row = row0 + hh * 8;
                float re = acc[mt][nt][2 * hh + 0];
                float im = acc[mt][nt][2 * hh + 1];
                if (rope) {
                    int t_ = row & (T_SEQ - 1);
                    int i_ = (col & 63) >> 1;
                    float2 c = cs[(t_ << 5) + i_];
                    float nre = re * c.x - im * c.y;
                    float nim = re * c.y + im * c.x;
                    re = nre; im = nim;
                }
                *(float2*)&C[(size_t)row * N + col] = make_float2(re, im);
            }
        }
    }
}

// ---------------- plain GEMM for the output projection ----------------
__global__ __launch_bounds__(256, 1) void gemm_tf32(
    const float* __restrict__ A, const float* __restrict__ B,
    float* __restrict__ C, int M, int N, int K)
{
    extern __shared__ float sm[];
    const int tid  = threadIdx.x;
    const int lane = tid & 31;
    const int w    = tid >> 5;
    const int wm   = w >> 2;
    const int wn   = w & 3;
    const int brow = blockIdx.y * BM;
    const int bcol = blockIdx.x * BN;

    float acc[4][8][4];
#pragma unroll
    for (int mt = 0; mt < 4; mt++)
#pragma unroll
        for (int nt = 0; nt < 8; nt++)
#pragma unroll
            for (int i = 0; i < 4; i++) acc[mt][nt][i] = 0.f;

    auto load_stage = [&](int s, int k0) {
        float* As = sm + s * STAGE_FLOATS;
        float* Bs = As + AS_FLOATS;
        const int kq = tid & 7;
        const int mbase = tid >> 3;
#pragma unroll
        for (int r = 0; r < 4; r++) {
            int m = mbase + 32 * r;
            cp16(&As[m * PA + 4 * kq], A + (size_t)(brow + m) * K + k0 + 4 * kq);
        }
#pragma unroll
        for (int r = 0; r < 4; r++) {
            int kk = w + 8 * r;
#pragma unroll
            for (int c = 0; c < 2; c++) {
                int n = 4 * lane + 128 * c;
                cp16(&Bs[kk * PB + n], B + (size_t)(k0 + kk) * N + bcol + n);
            }
        }
    };

    const int ntk = K / BK;
    load_stage(0, 0);   cp_commit();
    load_stage(1, BK);  cp_commit();

    const int aRow    = lane & 15;
    const int aColSel = (lane >> 4) * 4;
    const int tig     = lane & 3;
    const int g       = lane >> 2;

    for (int t = 0; t < ntk; t++) {
        cp_wait1();
        __syncthreads();
        float* As = sm + (t & 1) * STAGE_FLOATS;
        float* Bs = As + AS_FLOATS;
#pragma unroll
        for (int ks = 0; ks < 4; ks++) {
            uint32_t a[4][4];
#pragma unroll
            for (int mt = 0; mt < 4; mt++) {
                float* p = &As[(wm * 64 + mt * 16 + aRow) * PA + ks * 8 + aColSel];
                uint32_t sa = (uint32_t)__cvta_generic_to_shared(p);
                uint32_t r0, r1, r2, r3;
                asm volatile("ldmatrix.sync.aligned.m8n8.x4.shared.b16 {%0,%1,%2,%3}, [%4];"
                             : "=r"(r0), "=r"(r1), "=r"(r2), "=r"(r3) : "r"(sa));
                a[mt][0] = f2tf(__uint_as_float(r0));
                a[mt][1] = f2tf(__uint_as_float(r1));
                a[mt][2] = f2tf(__uint_as_float(r2));
                a[mt][3] = f2tf(__uint_as_float(r3));
            }
#pragma unroll
            for (int nt = 0; nt < 8; nt++) {
                int n = wn * 64 + nt * 8 + g;
                uint32_t b0 = f2tf(Bs[(ks * 8 + tig) * PB + n]);
                uint32_t b1 = f2tf(Bs[(ks * 8 + 4 + tig) * PB + n]);
#pragma unroll
                for (int mt = 0; mt < 4; mt++)
                    mma_tf32(acc[mt][nt], a[mt], b0, b1);
            }
        }
        __syncthreads();
        if (t + 2 < ntk) load_stage(t & 1, (t + 2) * BK);
        cp_commit();
    }

#pragma unroll
    for (int mt = 0; mt < 4; mt++) {
        int row = brow + wm * 64 + mt * 16 + g;
#pragma unroll
        for (int nt = 0; nt < 8; nt++) {
            int col = bcol + wn * 64 + nt * 8 + 2 * tig;
            *(float2*)&C[(size_t)row * N + col]       = make_float2(acc[mt][nt][0], acc[mt][nt][1]);
            *(float2*)&C[(size_t)(row + 8) * N + col] = make_float2(acc[mt][nt][2], acc[mt][nt][3]);
        }
    }
}

// ---------------- tensor-core causal flash attention ----------------
// Q tile 128 rows, K/V tiles 64 tokens. 8 warps, warp = 16 q-rows.
__global__ __launch_bounds__(256, 2) void flash_tc(
    const float* __restrict__ Q, const float* __restrict__ K,
    const float* __restrict__ V, float* __restrict__ O)
{
    extern __shared__ float sm[];
    float* Qs = sm;                       // [128][FP]   Q rows (pre-scaled)
    float* KP = sm + FQ * FP;             // [128][FP]   first 64 rows = K^T [d][j]; later P [i][j]
    float* Vs = sm + 2 * FQ * FP;         // [64][FP]    V [j][d]

    const int tid  = threadIdx.x;
    const int lane = tid & 31;
    const int w    = tid >> 5;
    const int g    = lane >> 2;
    const int tig  = lane & 3;

    const int qtile = blockIdx.x;
    const int h     = blockIdx.y;
    const int b     = blockIdx.z;
    const int kvh   = h >> 2;
    const size_t qtok0 = (size_t)b * T_SEQ + qtile * FQ;

    // load Q tile (scaled by 1/sqrt(64))
    {
        const int row = tid >> 4;        // stride 16 rows per 256 threads? -> loop
        const int c4  = tid & 15;
#pragma unroll
        for (int r = 0; r < 8; r++) {
            int rr = row + r * 16;
            float4 vq = *(const float4*)(Q + (qtok0 + rr) * HDIM + h * HD + c4 * 4);
            float* d = &Qs[rr * FP + c4 * 4];
            d[0] = vq.x * 0.125f; d[1] = vq.y * 0.125f;
            d[2] = vq.z * 0.125f; d[3] = vq.w * 0.125f;
        }
    }

    float m[2], l[2], oacc[8][4];
    m[0] = m[1] = -1e30f; l[0] = l[1] = 0.f;
#pragma unroll
    for (int nt = 0; nt < 8; nt++)
#pragma unroll
        for (int i = 0; i < 4; i++) oacc[nt][i] = 0.f;

    const int ktmax = 2 * qtile + 1;

    for (int kt = 0; kt <= ktmax; kt++) {
        const size_t ktok0 = (size_t)b * T_SEQ + kt * FK;
        __syncthreads();   // previous P/V reads done
        // load K (transposed -> KP[d][j]) and V (rows)
        {
            const int row = tid >> 4;
            const int c4  = tid & 15;
#pragma unroll
            for (int r = 0; r < 4; r++) {
                int rr = row + r * 16;
                float4 kv = *(const float4*)(K + (ktok0 + rr) * KVDIM + kvh * HD + c4 * 4);
                KP[(c4 * 4 + 0) * FP + rr] = kv.x;
                KP[(c4 * 4 + 1) * FP + rr] = kv.y;
                KP[(c4 * 4 + 2) * FP + rr] = kv.z;
                KP[(c4 * 4 + 3) * FP + rr] = kv.w;
                float4 vv = *(const float4*)(V + (ktok0 + rr) * KVDIM + kvh * HD + c4 * 4);
                *(float4*)&Vs[rr * FP + c4 * 4] = vv;
            }
        }
        __syncthreads();   // tiles ready

        // S = Q K^T  (warp rows w*16 .. w*16+15)
        float sacc[8][4];
#pragma unroll
        for (int nt = 0; nt < 8; nt++)
#pragma unroll
            for (int i = 0; i < 4; i++) sacc[nt][i] = 0.f;

        uint32_t af[8][4];
#pragma unroll
        for (int ks = 0; ks < 8; ks++) {
            const float* qb = &Qs[(w * 16 + g) * FP + ks * 8 + tig];
            af[ks][0] = f2tf(qb[0]);
            af[ks][1] = f2tf(qb[8 * FP]);
            af[ks][2] = f2tf(qb[4]);
            af[ks][3] = f2tf(qb[8 * FP + 4]);
        }
#pragma unroll
        for (int nt = 0; nt < 8; nt++) {
#pragma unroll
            for (int ks = 0; ks < 8; ks++) {
                uint32_t b0 = f2tf(KP[(ks * 8 + tig) * FP + nt * 8 + g]);
                uint32_t b1 = f2tf(KP[(ks * 8 + tig + 4) * FP + nt * 8 + g]);
                mma_tf32(sacc[nt], af[ks], b0, b1);
            }
        }

        // causal mask (only near the diagonal)
        if (kt >= 2 * qtile) {
#pragma unroll
            for (int nt = 0; nt < 8; nt++)
#pragma unroll
                for (int i = 0; i < 4; i++) {
                    int rowg = qtile * FQ + w * 16 + g + (i >> 1) * 8;
                    int colg = kt * FK + nt * 8 + 2 * tig + (i & 1);
                    if (colg > rowg) sacc[nt][i] = -1e30f;
                }
        }

        // online softmax (rows g and g+8)
        float fac[2];
#pragma unroll
        for (int hh = 0; hh < 2; hh++) {
            float mx = -1e30f;
#pragma unroll
            for (int nt = 0; nt < 8; nt++)
                mx = fmaxf(mx, fmaxf(sacc[nt][2 * hh], sacc[nt][2 * hh + 1]));
            mx = fmaxf(mx, __shfl_xor_sync(0xffffffffu, mx, 1));
            mx = fmaxf(mx, __shfl_xor_sync(0xffffffffu, mx, 2));
            float mn = fmaxf(m[hh], mx);
            fac[hh] = __expf(m[hh] - mn);
            m[hh] = mn;
            float rs = 0.f;
#pragma unroll
            for (int nt = 0; nt < 8; nt++) {
                float p0 = __expf(sacc[nt][2 * hh]     - mn);
                float p1 = __expf(sacc[nt][2 * hh + 1] - mn);
                sacc[nt][2 * hh] = p0; sacc[nt][2 * hh + 1] = p1;
                rs += p0 + p1;
            }
            rs += __shfl_xor_sync(0xffffffffu, rs, 1);
            rs += __shfl_xor_sync(0xffffffffu, rs, 2);
            l[hh] = l[hh] * fac[hh] + rs;
#pragma unroll
            for (int nt = 0; nt < 8; nt++) {
                oacc[nt][2 * hh]     *= fac[hh];
                oacc[nt][2 * hh + 1] *= fac[hh];
            }
        }

        __syncthreads();   // all warps done reading K
        // store P over the KP region: P[i][j], i = q row (128), j = kv token (64)
#pragma unroll
        for (int nt = 0; nt < 8; nt++) {
            *(float2*)&KP[(w * 16 + g)     * FP + nt * 8 + 2 * tig] = make_float2(sacc[nt][0], sacc[nt][1]);
            *(float2*)&KP[(w * 16 + g + 8) * FP + nt * 8 + 2 * tig] = make_float2(sacc[nt][2], sacc[nt][3]);
        }
        __syncthreads();   // P ready

        // O += P V
        uint32_t pf[8][4];
#pragma unroll
        for (int ks = 0; ks < 8; ks++) {
            const float* pb = &KP[(w * 16 + g) * FP + ks * 8 + tig];
            pf[ks][0] = f2tf(pb[0]);
            pf[ks][1] = f2tf(pb[8 * FP]);
            pf[ks][2] = f2tf(pb[4]);
            pf[ks][3] = f2tf(pb[8 * FP + 4]);
        }
#pragma unroll
        for (int nt = 0; nt < 8; nt++) {
#pragma unroll
            for (int ks = 0; ks < 8; ks++) {
                uint32_t b0 = f2tf(Vs[(ks * 8 + tig) * FP + nt * 8 + g]);
                uint32_t b1 = f2tf(Vs[(ks * 8 + tig + 4) * FP + nt * 8 + g]);
                mma_tf32(oacc[nt], pf[ks], b0, b1);
            }
        }
    }

    // epilogue
    float inv0 = 1.0f / l[0], inv1 = 1.0f / l[1];
#pragma unroll
    for (int nt = 0; nt < 8; nt++) {
        size_t row0 = qtok0 + w * 16 + g;
        int col = h * HD + nt * 8 + 2 * tig;
        *(float2*)&O[row0 * HDIM + col]       = make_float2(oacc[nt][0] * inv0, oacc[nt][1] * inv0);
        *(float2*)&O[(row0 + 8) * HDIM + col] = make_float2(oacc[nt][2] * inv1, oacc[nt][3] * inv1);
    }
}

// ---------------- launch ----------------
extern "C" void kernel_launch(void* const* d_in, const int* in_sizes, int n_in,
                              void* d_out, int out_size) {
    const float* x  = (const float*)d_in[0];
    const float* wq = (const float*)d_in[1];
    const float* wk = (const float*)d_in[2];
    const float* wv = (const float*)d_in[3];
    const float* wo = (const float*)d_in[4];
    float* out = (float*)d_out;

    float *q, *k, *v, *attn;
    float2* cs;
    cudaGetSymbolAddress((void**)&q,    g_q);
    cudaGetSymbolAddress((void**)&k,    g_k);
    cudaGetSymbolAddress((void**)&v,    g_v);
    cudaGetSymbolAddress((void**)&attn, g_attn);
    cudaGetSymbolAddress((void**)&cs,   g_cs);

    cudaFuncSetAttribute(gemm_qkv,  cudaFuncAttributeMaxDynamicSharedMemorySize, GEMM_SMEM);
    cudaFuncSetAttribute(gemm_tf32, cudaFuncAttributeMaxDynamicSharedMemorySize, GEMM_SMEM);
    cudaFuncSetAttribute(flash_tc,  cudaFuncAttributeMaxDynamicSharedMemorySize, FLASH_SMEM);

    cossin_kernel<<<(T_SEQ * 32) / 256, 256>>>(cs);

    gemm_qkv<<<dim3(12, NTOK / BM), 256, GEMM_SMEM>>>(x, wq, wk, wv, q, k, v, cs);

    flash_tc<<<dim3(T_SEQ / FQ, NH, 2), 256, FLASH_SMEM>>>(q, k, v, attn);

    gemm_tf32<<<dim3(HDIM / BN, NTOK / BM), 256, GEMM_SMEM>>>(attn, wo, out, NTOK, HDIM, HDIM);
}

// round 4
// speedup vs baseline: 3.3072x; 1.2436x over previous
#include <cuda_runtime.h>
#include <math.h>
#include <stdint.h>

#define T_SEQ 2048
#define HDIM  2048
#define NH    32
#define NKVH  8
#define HD    64
#define NTOK  4096
#define KVDIM (NKVH*HD)

// ---------------- GEMM tile params ----------------
#define BM 128
#define BN 256
#define BK 32
#define PA 36
#define PB 264
#define AS_FLOATS (BM*PA)
#define BS_FLOATS (BK*PB)
#define STAGE_FLOATS (AS_FLOATS + BS_FLOATS)
#define GEMM_SMEM (2*STAGE_FLOATS*4)

// ---------------- flash params ----------------
#define FQ 128
#define FK 64
#define QP 68     // pitch (u32) for Qs/Ks/Ps: frag pattern 4g+tig -> conflict-free
#define VP 72     // pitch (u32) for Vs: frag pattern 8tig+g -> conflict-free
#define FLASH_SMEM ((FQ*QP + FK*QP + FQ*QP + FK*VP)*4)   // 105472 B

// ---------------- scratch ----------------
__device__ float  g_q[NTOK * HDIM];
__device__ float  g_k[NTOK * KVDIM];
__device__ float  g_v[NTOK * KVDIM];
__device__ float  g_attn[NTOK * HDIM];
__device__ float2 g_cs[T_SEQ * 32];

// ---------------- cos/sin (cheap, no FP64 transcendentals) ----------------
__global__ void cossin_kernel(float2* __restrict__ cs) {
    int idx = blockIdx.x * blockDim.x + threadIdx.x;
    int t = idx >> 5;
    int i = idx & 31;
    const double r = 0.74989420933245582;   // 10000^(-1/32)
    double inv = 1.0;
    for (int j = 0; j < i; j++) inv *= r;
    double f = (double)t * inv;
    double kq = rint(f * 0.15915494309189535);       // f / (2*pi)
    double rem = f - kq * 6.283185307179586476925287;
    float fr = (float)rem;
    cs[idx] = make_float2(cosf(fr), sinf(fr));
}

// ---------------- helpers ----------------
__device__ __forceinline__ void cp16(float* s, const float* g) {
    uint32_t sa = (uint32_t)__cvta_generic_to_shared(s);
    asm volatile("cp.async.cg.shared.global [%0], [%1], 16;" :: "r"(sa), "l"(g));
}
__device__ __forceinline__ void cp_commit() { asm volatile("cp.async.commit_group;"); }
__device__ __forceinline__ void cp_wait1()  { asm volatile("cp.async.wait_group 1;"); }
__device__ __forceinline__ uint32_t f2tf(float f) {
    uint32_t r;
    asm("cvt.rna.tf32.f32 %0, %1;" : "=r"(r) : "f"(f));
    return r;
}
__device__ __forceinline__ void mma_tf32(float* c, const uint32_t* a, uint32_t b0, uint32_t b1) {
    asm volatile(
        "mma.sync.aligned.m16n8k8.row.col.f32.tf32.tf32.f32 "
        "{%0,%1,%2,%3}, {%4,%5,%6,%7}, {%8,%9}, {%0,%1,%2,%3};"
        : "+f"(c[0]), "+f"(c[1]), "+f"(c[2]), "+f"(c[3])
        : "r"(a[0]), "r"(a[1]), "r"(a[2]), "r"(a[3]), "r"(b0), "r"(b1));
}
__device__ __forceinline__ uint4 cvt4(float4 v) {
    uint4 u;
    u.x = f2tf(v.x); u.y = f2tf(v.y); u.z = f2tf(v.z); u.w = f2tf(v.w);
    return u;
}

// ---------------- fused QKV GEMM (tf32) with RoPE epilogue ----------------
__global__ __launch_bounds__(256, 1) void gemm_qkv(
    const float* __restrict__ A,
    const float* __restrict__ wq, const float* __restrict__ wk, const float* __restrict__ wv,
    float* __restrict__ q, float* __restrict__ k, float* __restrict__ v,
    const float2* __restrict__ cs)
{
    extern __shared__ float sm[];
    const int bx = blockIdx.x;
    int bcol, N;
    const float *B; float *C; bool rope;
    if (bx < 8)       { bcol = bx * BN;        N = HDIM;  B = wq; C = q; rope = true;  }
    else if (bx < 10) { bcol = (bx - 8) * BN;  N = KVDIM; B = wk; C = k; rope = true;  }
    else              { bcol = (bx - 10) * BN; N = KVDIM; B = wv; C = v; rope = false; }
    const int K = HDIM;

    const int tid  = threadIdx.x;
    const int lane = tid & 31;
    const int w    = tid >> 5;
    const int wm   = w >> 2;
    const int wn   = w & 3;
    const int brow = blockIdx.y * BM;

    float acc[4][8][4];
#pragma unroll
    for (int mt = 0; mt < 4; mt++)
#pragma unroll
        for (int nt = 0; nt < 8; nt++)
#pragma unroll
            for (int i = 0; i < 4; i++) acc[mt][nt][i] = 0.f;

    auto load_stage = [&](int s, int k0) {
        float* As = sm + s * STAGE_FLOATS;
        float* Bs = As + AS_FLOATS;
        const int kq = tid & 7;
        const int mbase = tid >> 3;
#pragma unroll
        for (int r = 0; r < 4; r++) {
            int m = mbase + 32 * r;
            cp16(&As[m * PA + 4 * kq], A + (size_t)(brow + m) * K + k0 + 4 * kq);
        }
#pragma unroll
        for (int r = 0; r < 4; r++) {
            int kk = w + 8 * r;
#pragma unroll
            for (int c = 0; c < 2; c++) {
                int n = 4 * lane + 128 * c;
                cp16(&Bs[kk * PB + n], B + (size_t)(k0 + kk) * N + bcol + n);
            }
        }
    };

    const int ntk = K / BK;
    load_stage(0, 0);   cp_commit();
    load_stage(1, BK);  cp_commit();

    const int aRow    = lane & 15;
    const int aColSel = (lane >> 4) * 4;
    const int tig     = lane & 3;
    const int g       = lane >> 2;

    for (int t = 0; t < ntk; t++) {
        cp_wait1();
        __syncthreads();
        float* As = sm + (t & 1) * STAGE_FLOATS;
        float* Bs = As + AS_FLOATS;
#pragma unroll
        for (int ks = 0; ks < 4; ks++) {
            uint32_t a[4][4];
#pragma unroll
            for (int mt = 0; mt < 4; mt++) {
                float* p = &As[(wm * 64 + mt * 16 + aRow) * PA + ks * 8 + aColSel];
                uint32_t sa = (uint32_t)__cvta_generic_to_shared(p);
                uint32_t r0, r1, r2, r3;
                asm volatile("ldmatrix.sync.aligned.m8n8.x4.shared.b16 {%0,%1,%2,%3}, [%4];"
                             : "=r"(r0), "=r"(r1), "=r"(r2), "=r"(r3) : "r"(sa));
                a[mt][0] = f2tf(__uint_as_float(r0));
                a[mt][1] = f2tf(__uint_as_float(r1));
                a[mt][2] = f2tf(__uint_as_float(r2));
                a[mt][3] = f2tf(__uint_as_float(r3));
            }
#pragma unroll
            for (int nt = 0; nt < 8; nt++) {
                int n = wn * 64 + nt * 8 + g;
                uint32_t b0 = f2tf(Bs[(ks * 8 + tig) * PB + n]);
                uint32_t b1 = f2tf(Bs[(ks * 8 + 4 + tig) * PB + n]);
#pragma unroll
                for (int mt = 0; mt < 4; mt++)
                    mma_tf32(acc[mt][nt], a[mt], b0, b1);
            }
        }
        __syncthreads();
        if (t + 2 < ntk) load_stage(t & 1, (t + 2) * BK);
        cp_commit();
    }

#pragma unroll
    for (int mt = 0; mt < 4; mt++) {
        int row0 = brow + wm * 64 + mt * 16 + g;
#pragma unroll
        for (int nt = 0; nt < 8; nt++) {
            int col = bcol + wn * 64 + nt * 8 + 2 * tig;
#pragma unroll
            for (int hh = 0; hh < 2; hh++) {
                int row = row0 + hh * 8;
                float re = acc[mt][nt][2 * hh + 0];
                float im = acc[mt][nt][2 * hh + 1];
                if (rope) {
                    int t_ = row & (T_SEQ - 1);
                    int i_ = (col & 63) >> 1;
                    float2 c = cs[(t_ << 5) + i_];
                    float nre = re * c.x - im * c.y;
                    float nim = re * c.y + im * c.x;
                    re = nre; im = nim;
                }
                *(float2*)&C[(size_t)row * N + col] = make_float2(re, im);
            }
        }
    }
}

// ---------------- plain GEMM for the output projection ----------------
__global__ __launch_bounds__(256, 1) void gemm_tf32(
    const float* __restrict__ A, const float* __restrict__ B,
    float* __restrict__ C, int M, int N, int K)
{
    extern __shared__ float sm[];
    const int tid  = threadIdx.x;
    const int lane = tid & 31;
    const int w    = tid >> 5;
    const int wm   = w >> 2;
    const int wn   = w & 3;
    const int brow = blockIdx.y * BM;
    const int bcol = blockIdx.x * BN;

    float acc[4][8][4];
#pragma unroll
    for (int mt = 0; mt < 4; mt++)
#pragma unroll
        for (int nt = 0; nt < 8; nt++)
#pragma unroll
            for (int i = 0; i < 4; i++) acc[mt][nt][i] = 0.f;

    auto load_stage = [&](int s, int k0) {
        float* As = sm + s * STAGE_FLOATS;
        float* Bs = As + AS_FLOATS;
        const int kq = tid & 7;
        const int mbase = tid >> 3;
#pragma unroll
        for (int r = 0; r < 4; r++) {
            int m = mbase + 32 * r;
            cp16(&As[m * PA + 4 * kq], A + (size_t)(brow + m) * K + k0 + 4 * kq);
        }
#pragma unroll
        for (int r = 0; r < 4; r++) {
            int kk = w + 8 * r;
#pragma unroll
            for (int c = 0; c < 2; c++) {
                int n = 4 * lane + 128 * c;
                cp16(&Bs[kk * PB + n], B + (size_t)(k0 + kk) * N + bcol + n);
            }
        }
    };

    const int ntk = K / BK;
    load_stage(0, 0);   cp_commit();
    load_stage(1, BK);  cp_commit();

    const int aRow    = lane & 15;
    const int aColSel = (lane >> 4) * 4;
    const int tig     = lane & 3;
    const int g       = lane >> 2;

    for (int t = 0; t < ntk; t++) {
        cp_wait1();
        __syncthreads();
        float* As = sm + (t & 1) * STAGE_FLOATS;
        float* Bs = As + AS_FLOATS;
#pragma unroll
        for (int ks = 0; ks < 4; ks++) {
            uint32_t a[4][4];
#pragma unroll
            for (int mt = 0; mt < 4; mt++) {
                float* p = &As[(wm * 64 + mt * 16 + aRow) * PA + ks * 8 + aColSel];
                uint32_t sa = (uint32_t)__cvta_generic_to_shared(p);
                uint32_t r0, r1, r2, r3;
                asm volatile("ldmatrix.sync.aligned.m8n8.x4.shared.b16 {%0,%1,%2,%3}, [%4];"
                             : "=r"(r0), "=r"(r1), "=r"(r2), "=r"(r3) : "r"(sa));
                a[mt][0] = f2tf(__uint_as_float(r0));
                a[mt][1] = f2tf(__uint_as_float(r1));
                a[mt][2] = f2tf(__uint_as_float(r2));
                a[mt][3] = f2tf(__uint_as_float(r3));
            }
#pragma unroll
            for (int nt = 0; nt < 8; nt++) {
                int n = wn * 64 + nt * 8 + g;
                uint32_t b0 = f2tf(Bs[(ks * 8 + tig) * PB + n]);
                uint32_t b1 = f2tf(Bs[(ks * 8 + 4 + tig) * PB + n]);
#pragma unroll
                for (int mt = 0; mt < 4; mt++)
                    mma_tf32(acc[mt][nt], a[mt], b0, b1);
            }
        }
        __syncthreads();
        if (t + 2 < ntk) load_stage(t & 1, (t + 2) * BK);
        cp_commit();
    }

#pragma unroll
    for (int mt = 0; mt < 4; mt++) {
        int row = brow + wm * 64 + mt * 16 + g;
#pragma unroll
        for (int nt = 0; nt < 8; nt++) {
            int col = bcol + wn * 64 + nt * 8 + 2 * tig;
            *(float2*)&C[(size_t)row * N + col]       = make_float2(acc[mt][nt][0], acc[mt][nt][1]);
            *(float2*)&C[(size_t)(row + 8) * N + col] = make_float2(acc[mt][nt][2], acc[mt][nt][3]);
        }
    }
}

// ---------------- tensor-core causal flash attention (tf32 in smem) ----------------
__global__ __launch_bounds__(256, 2) void flash_tc(
    const float* __restrict__ Q, const float* __restrict__ K,
    const float* __restrict__ V, float* __restrict__ O)
{
    extern __shared__ uint32_t smu[];
    uint32_t* Qs = smu;                          // [128][QP]
    uint32_t* Ks = smu + FQ * QP;                // [64][QP]  row-major [j][d]
    uint32_t* Ps = smu + FQ * QP + FK * QP;      // [128][QP]
    uint32_t* Vs = smu + 2 * FQ * QP + FK * QP;  // [64][VP]  row-major [j][d]

    const int tid  = threadIdx.x;
    const int lane = tid & 31;
    const int w    = tid >> 5;
    const int g    = lane >> 2;
    const int tig  = lane & 3;

    const int qtile = blockIdx.x;
    const int h     = blockIdx.y;
    const int b     = blockIdx.z;
    const int kvh   = h >> 2;
    const size_t qtok0 = (size_t)b * T_SEQ + qtile * FQ;

    // load Q tile, scale, convert to tf32 once
    {
        const int row = tid >> 4;
        const int c4  = tid & 15;
#pragma unroll
        for (int r = 0; r < 8; r++) {
            int rr = row + r * 16;
            float4 vq = *(const float4*)(Q + (qtok0 + rr) * HDIM + h * HD + c4 * 4);
            vq.x *= 0.125f; vq.y *= 0.125f; vq.z *= 0.125f; vq.w *= 0.125f;
            *(uint4*)&Qs[rr * QP + c4 * 4] = cvt4(vq);
        }
    }

    float m[2], l[2], oacc[8][4];
    m[0] = m[1] = -1e30f; l[0] = l[1] = 0.f;
#pragma unroll
    for (int nt = 0; nt < 8; nt++)
#pragma unroll
        for (int i = 0; i < 4; i++) oacc[nt][i] = 0.f;

    const int ktmax = 2 * qtile + 1;

    for (int kt = 0; kt <= ktmax; kt++) {
        const size_t ktok0 = (size_t)b * T_SEQ + kt * FK;
        __syncthreads();   // prev iteration's K/V reads done (also covers Q store on kt=0)
        {
            const int row = tid >> 4;
            const int c4  = tid & 15;
#pragma unroll
            for (int r = 0; r < 4; r++) {
                int rr = row + r * 16;
                float4 kv = *(const float4*)(K + (ktok0 + rr) * KVDIM + kvh * HD + c4 * 4);
                *(uint4*)&Ks[rr * QP + c4 * 4] = cvt4(kv);
                float4 vv = *(const float4*)(V + (ktok0 + rr) * KVDIM + kvh * HD + c4 * 4);
                *(uint4*)&Vs[rr * VP + c4 * 4] = cvt4(vv);
            }
        }
        __syncthreads();   // tiles ready

        // S = Q K^T
        float sacc[8][4];
#pragma unroll
        for (int nt = 0; nt < 8; nt++)
#pragma unroll
            for (int i = 0; i < 4; i++) sacc[nt][i] = 0.f;

#pragma unroll
        for (int ks = 0; ks < 8; ks++) {
            uint32_t af[4];
            const uint32_t* qb = &Qs[(w * 16 + g) * QP + ks * 8 + tig];
            af[0] = qb[0];
            af[1] = qb[8 * QP];
            af[2] = qb[4];
            af[3] = qb[8 * QP + 4];
#pragma unroll
            for (int nt = 0; nt < 8; nt++) {
                uint32_t b0 = Ks[(nt * 8 + g) * QP + ks * 8 + tig];
                uint32_t b1 = Ks[(nt * 8 + g) * QP + ks * 8 + tig + 4];
                mma_tf32(sacc[nt], af, b0, b1);
            }
        }

        // causal mask near the diagonal
        if (kt >= 2 * qtile) {
#pragma unroll
            for (int nt = 0; nt < 8; nt++)
#pragma unroll
                for (int i = 0; i < 4; i++) {
                    int rowg = qtile * FQ + w * 16 + g + (i >> 1) * 8;
                    int colg = kt * FK + nt * 8 + 2 * tig + (i & 1);
                    if (colg > rowg) sacc[nt][i] = -1e30f;
                }
        }

        // online softmax (rows g and g+8)
#pragma unroll
        for (int hh = 0; hh < 2; hh++) {
            float mx = -1e30f;
#pragma unroll
            for (int nt = 0; nt < 8; nt++)
                mx = fmaxf(mx, fmaxf(sacc[nt][2 * hh], sacc[nt][2 * hh + 1]));
            mx = fmaxf(mx, __shfl_xor_sync(0xffffffffu, mx, 1));
            mx = fmaxf(mx, __shfl_xor_sync(0xffffffffu, mx, 2));
            float mn = fmaxf(m[hh], mx);
            float fac = __expf(m[hh] - mn);
            m[hh] = mn;
            float rs = 0.f;
#pragma unroll
            for (int nt = 0; nt < 8; nt++) {
                float p0 = __expf(sacc[nt][2 * hh]     - mn);
                float p1 = __expf(sacc[nt][2 * hh + 1] - mn);
                sacc[nt][2 * hh] = p0; sacc[nt][2 * hh + 1] = p1;
                rs += p0 + p1;
            }
            rs += __shfl_xor_sync(0xffffffffu, rs, 1);
            rs += __shfl_xor_sync(0xffffffffu, rs, 2);
            l[hh] = l[hh] * fac + rs;
#pragma unroll
            for (int nt = 0; nt < 8; nt++) {
                oacc[nt][2 * hh]     *= fac;
                oacc[nt][2 * hh + 1] *= fac;
            }
        }

        // store P (tf32) — warp-private region, only warp-level sync needed
#pragma unroll
        for (int nt = 0; nt < 8; nt++) {
            uint2 p01, p23;
            p01.x = f2tf(sacc[nt][0]); p01.y = f2tf(sacc[nt][1]);
            p23.x = f2tf(sacc[nt][2]); p23.y = f2tf(sacc[nt][3]);
            *(uint2*)&Ps[(w * 16 + g)     * QP + nt * 8 + 2 * tig] = p01;
            *(uint2*)&Ps[(w * 16 + g + 8) * QP + nt * 8 + 2 * tig] = p23;
        }
        __syncwarp();

        // O += P V
#pragma unroll
        for (int ks = 0; ks < 8; ks++) {
            uint32_t pf[4];
            const uint32_t* pb = &Ps[(w * 16 + g) * QP + ks * 8 + tig];
            pf[0] = pb[0];
            pf[1] = pb[8 * QP];
            pf[2] = pb[4];
            pf[3] = pb[8 * QP + 4];
#pragma unroll
            for (int nt = 0; nt < 8; nt++) {
                uint32_t b0 = Vs[(ks * 8 + tig) * VP + nt * 8 + g];
                uint32_t b1 = Vs[(ks * 8 + tig + 4) * VP + nt * 8 + g];
                mma_tf32(oacc[nt], pf, b0, b1);
            }
        }
    }

    // epilogue
    float inv0 = 1.0f / l[0], inv1 = 1.0f / l[1];
#pragma unroll
    for (int nt = 0; nt < 8; nt++) {
        size_t row0 = qtok0 + w * 16 + g;
        int col = h * HD + nt * 8 + 2 * tig;
        *(float2*)&O[row0 * HDIM + col]       = make_float2(oacc[nt][0] * inv0, oacc[nt][1] * inv0);
        *(float2*)&O[(row0 + 8) * HDIM + col] = make_float2(oacc[nt][2] * inv1, oacc[nt][3] * inv1);
    }
}

// ---------------- launch ----------------
extern "C" void kernel_launch(void* const* d_in, const int* in_sizes, int n_in,
                              void* d_out, int out_size) {
    const float* x  = (const float*)d_in[0];
    const float* wq = (const float*)d_in[1];
    const float* wk = (const float*)d_in[2];
    const float* wv = (const float*)d_in[3];
    const float* wo = (const float*)d_in[4];
    float* out = (float*)d_out;

    float *q, *k, *v, *attn;
    float2* cs;
    cudaGetSymbolAddress((void**)&q,    g_q);
    cudaGetSymbolAddress((void**)&k,    g_k);
    cudaGetSymbolAddress((void**)&v,    g_v);
    cudaGetSymbolAddress((void**)&attn, g_attn);
    cudaGetSymbolAddress((void**)&cs,   g_cs);

    cudaFuncSetAttribute(gemm_qkv,  cudaFuncAttributeMaxDynamicSharedMemorySize, GEMM_SMEM);
    cudaFuncSetAttribute(gemm_tf32, cudaFuncAttributeMaxDynamicSharedMemorySize, GEMM_SMEM);
    cudaFuncSetAttribute(flash_tc,  cudaFuncAttributeMaxDynamicSharedMemorySize, FLASH_SMEM);

    cossin_kernel<<<(T_SEQ * 32) / 256, 256>>>(cs);

    gemm_qkv<<<dim3(12, NTOK / BM), 256, GEMM_SMEM>>>(x, wq, wk, wv, q, k, v, cs);

    flash_tc<<<dim3(T_SEQ / FQ, NH, 2), 256, FLASH_SMEM>>>(q, k, v, attn);

    gemm_tf32<<<dim3(HDIM / BN, NTOK / BM), 256, GEMM_SMEM>>>(attn, wo, out, NTOK, HDIM, HDIM);
}

// round 5
// speedup vs baseline: 3.4239x; 1.0353x over previous
#include <cuda_runtime.h>
#include <math.h>
#include <stdint.h>

#define T_SEQ 2048
#define HDIM  2048
#define NH    32
#define NKVH  8
#define HD    64
#define NTOK  4096
#define KVDIM (NKVH*HD)

// ---------------- GEMM tile params ----------------
#define BM 128
#define BN 256
#define BK 32
#define PA 36
#define PB 264
#define AS_U32 (BM*PA)
#define BS_U32 (BK*PB)
#define STAGE_U32 (AS_U32 + BS_U32)
#define GEMM_SMEM (2*STAGE_U32*4)

// ---------------- flash params ----------------
#define FQ 128
#define FK 64
#define QP 68
#define VP 72
#define FLASH_SMEM ((FQ*QP + FK*QP + FQ*QP + FK*VP)*4)

// ---------------- scratch (tf32 bit domain) ----------------
__device__ uint32_t g_x [NTOK * HDIM];
__device__ uint32_t g_wq[HDIM * HDIM];
__device__ uint32_t g_wk[HDIM * KVDIM];
__device__ uint32_t g_wv[HDIM * KVDIM];
__device__ uint32_t g_wo[HDIM * HDIM];
__device__ uint32_t g_q [NTOK * HDIM];
__device__ uint32_t g_k [NTOK * KVDIM];
__device__ uint32_t g_v [NTOK * KVDIM];
__device__ uint32_t g_attn[NTOK * HDIM];
__device__ float2   g_cs[T_SEQ * 32];

// ---------------- helpers ----------------
__device__ __forceinline__ uint32_t f2tf(float f) {
    uint32_t r;
    asm("cvt.rna.tf32.f32 %0, %1;" : "=r"(r) : "f"(f));
    return r;
}
__device__ __forceinline__ uint4 cvt4(float4 v) {
    uint4 u;
    u.x = f2tf(v.x); u.y = f2tf(v.y); u.z = f2tf(v.z); u.w = f2tf(v.w);
    return u;
}
__device__ __forceinline__ void cp16(uint32_t* s, const uint32_t* g) {
    uint32_t sa = (uint32_t)__cvta_generic_to_shared(s);
    asm volatile("cp.async.cg.shared.global [%0], [%1], 16;" :: "r"(sa), "l"(g));
}
__device__ __forceinline__ void cp_commit() { asm volatile("cp.async.commit_group;"); }
__device__ __forceinline__ void cp_wait1()  { asm volatile("cp.async.wait_group 1;"); }
__device__ __forceinline__ void mma_tf32(float* c, const uint32_t* a, uint32_t b0, uint32_t b1) {
    asm volatile(
        "mma.sync.aligned.m16n8k8.row.col.f32.tf32.tf32.f32 "
        "{%0,%1,%2,%3}, {%4,%5,%6,%7}, {%8,%9}, {%0,%1,%2,%3};"
        : "+f"(c[0]), "+f"(c[1]), "+f"(c[2]), "+f"(c[3])
        : "r"(a[0]), "r"(a[1]), "r"(a[2]), "r"(a[3]), "r"(b0), "r"(b1));
}

// ---------------- fp32 -> tf32 bits bulk convert ----------------
__global__ void cvt_tf32_kernel(const float4* __restrict__ src, uint4* __restrict__ dst, int n4) {
    int i = blockIdx.x * blockDim.x + threadIdx.x;
    if (i < n4) dst[i] = cvt4(src[i]);
}

// ---------------- cos/sin ----------------
__global__ void cossin_kernel(float2* __restrict__ cs) {
    int idx = blockIdx.x * blockDim.x + threadIdx.x;
    int t = idx >> 5;
    int i = idx & 31;
    const double r = 0.74989420933245582;   // 10000^(-1/32)
    double inv = 1.0;
    for (int j = 0; j < i; j++) inv *= r;
    double f = (double)t * inv;
    double kq = rint(f * 0.15915494309189535);
    double rem = f - kq * 6.283185307179586476925287;
    float fr = (float)rem;
    cs[idx] = make_float2(cosf(fr), sinf(fr));
}

// ---------------- shared GEMM mainloop (u32 tf32 operands) ----------------
struct GemmCore {
    float acc[4][8][4];
    const uint32_t* A; const uint32_t* B;
    int N, K, brow, bcol, tid, lane, w, wm, wn;
    uint32_t* sm;

    __device__ __forceinline__ void load_stage(int s, int k0) {
        uint32_t* As = sm + s * STAGE_U32;
        uint32_t* Bs = As + AS_U32;
        const int kq = tid & 7;
        const int mbase = tid >> 3;
#pragma unroll
        for (int r = 0; r < 4; r++) {
            int m = mbase + 32 * r;
            cp16(&As[m * PA + 4 * kq], A + (size_t)(brow + m) * K + k0 + 4 * kq);
        }
#pragma unroll
        for (int r = 0; r < 4; r++) {
            int kk = w + 8 * r;
#pragma unroll
            for (int c = 0; c < 2; c++) {
                int n = 4 * lane + 128 * c;
                cp16(&Bs[kk * PB + n], B + (size_t)(k0 + kk) * N + bcol + n);
            }
        }
    }

    __device__ __forceinline__ void run() {
#pragma unroll
        for (int mt = 0; mt < 4; mt++)
#pragma unroll
            for (int nt = 0; nt < 8; nt++)
#pragma unroll
                for (int i = 0; i < 4; i++) acc[mt][nt][i] = 0.f;

        const int ntk = K / BK;
        load_stage(0, 0);   cp_commit();
        load_stage(1, BK);  cp_commit();

        const int aRow    = lane & 15;
        const int aColSel = (lane >> 4) * 4;
        const int tig     = lane & 3;
        const int g       = lane >> 2;

        for (int t = 0; t < ntk; t++) {
            cp_wait1();
            __syncthreads();
            uint32_t* As = sm + (t & 1) * STAGE_U32;
            uint32_t* Bs = As + AS_U32;
#pragma unroll
            for (int ks = 0; ks < 4; ks++) {
                uint32_t a[4][4];
#pragma unroll
                for (int mt = 0; mt < 4; mt++) {
                    uint32_t* p = &As[(wm * 64 + mt * 16 + aRow) * PA + ks * 8 + aColSel];
                    uint32_t sa = (uint32_t)__cvta_generic_to_shared(p);
                    asm volatile("ldmatrix.sync.aligned.m8n8.x4.shared.b16 {%0,%1,%2,%3}, [%4];"
                                 : "=r"(a[mt][0]), "=r"(a[mt][1]), "=r"(a[mt][2]), "=r"(a[mt][3])
                                 : "r"(sa));
                }
#pragma unroll
                for (int nt = 0; nt < 8; nt++) {
                    int n = wn * 64 + nt * 8 + g;
                    uint32_t b0 = Bs[(ks * 8 + tig) * PB + n];
                    uint32_t b1 = Bs[(ks * 8 + 4 + tig) * PB + n];
#pragma unroll
                    for (int mt = 0; mt < 4; mt++)
                        mma_tf32(acc[mt][nt], a[mt], b0, b1);
                }
            }
            __syncthreads();
            if (t + 2 < ntk) load_stage(t & 1, (t + 2) * BK);
            cp_commit();
        }
    }
};

// ---------------- fused QKV GEMM with RoPE epilogue, tf32-bits out ----------------
__global__ __launch_bounds__(256, 1) void gemm_qkv(
    const uint32_t* __restrict__ A,
    const uint32_t* __restrict__ wq, const uint32_t* __restrict__ wk, const uint32_t* __restrict__ wv,
    uint32_t* __restrict__ q, uint32_t* __restrict__ k, uint32_t* __restrict__ v,
    const float2* __restrict__ cs)
{
    extern __shared__ uint32_t smu[];
    const int bx = blockIdx.x;
    int bcol, N;
    const uint32_t* B; uint32_t* C; bool rope; float scale;
    if (bx < 8)       { bcol = bx * BN;        N = HDIM;  B = wq; C = q; rope = true;  scale = 0.125f; }
    else if (bx < 10) { bcol = (bx - 8) * BN;  N = KVDIM; B = wk; C = k; rope = true;  scale = 1.f; }
    else              { bcol = (bx - 10) * BN; N = KVDIM; B = wv; C = v; rope = false; scale = 1.f; }

    GemmCore gc;
    gc.A = A; gc.B = B; gc.N = N; gc.K = HDIM;
    gc.brow = blockIdx.y * BM; gc.bcol = bcol;
    gc.tid = threadIdx.x; gc.lane = gc.tid & 31; gc.w = gc.tid >> 5;
    gc.wm = gc.w >> 2; gc.wn = gc.w & 3; gc.sm = smu;
    gc.run();

    const int tig = gc.lane & 3;
    const int g   = gc.lane >> 2;
#pragma unroll
    for (int mt = 0; mt < 4; mt++) {
        int row0 = gc.brow + gc.wm * 64 + mt * 16 + g;
#pragma unroll
        for (int nt = 0; nt < 8; nt++) {
            int col = bcol + gc.wn * 64 + nt * 8 + 2 * tig;
#pragma unroll
            for (int hh = 0; hh < 2; hh++) {
                int row = row0 + hh * 8;
                float re = gc.acc[mt][nt][2 * hh + 0];
                float im = gc.acc[mt][nt][2 * hh + 1];
                if (rope) {
                    int t_ = row & (T_SEQ - 1);
                    int i_ = (col & 63) >> 1;
                    float2 c = cs[(t_ << 5) + i_];
                    float nre = re * c.x - im * c.y;
                    float nim = re * c.y + im * c.x;
                    re = nre; im = nim;
                }
                re *= scale; im *= scale;
                uint2 u = make_uint2(f2tf(re), f2tf(im));
                *(uint2*)&C[(size_t)row * N + col] = u;
            }
        }
    }
}

// ---------------- output projection GEMM: u32 in, fp32 out ----------------
__global__ __launch_bounds__(256, 1) void gemm_wo(
    const uint32_t* __restrict__ A, const uint32_t* __restrict__ B,
    float* __restrict__ C)
{
    extern __shared__ uint32_t smu[];
    GemmCore gc;
    gc.A = A; gc.B = B; gc.N = HDIM; gc.K = HDIM;
    gc.brow = blockIdx.y * BM; gc.bcol = blockIdx.x * BN;
    gc.tid = threadIdx.x; gc.lane = gc.tid & 31; gc.w = gc.tid >> 5;
    gc.wm = gc.w >> 2; gc.wn = gc.w & 3; gc.sm = smu;
    gc.run();

    const int tig = gc.lane & 3;
    const int g   = gc.lane >> 2;
#pragma unroll
    for (int mt = 0; mt < 4; mt++) {
        int row = gc.brow + gc.wm * 64 + mt * 16 + g;
#pragma unroll
        for (int nt = 0; nt < 8; nt++) {
            int col = gc.bcol + gc.wn * 64 + nt * 8 + 2 * tig;
            *(float2*)&C[(size_t)row * HDIM + col]       = make_float2(gc.acc[mt][nt][0], gc.acc[mt][nt][1]);
            *(float2*)&C[(size_t)(row + 8) * HDIM + col] = make_float2(gc.acc[mt][nt][2], gc.acc[mt][nt][3]);
        }
    }
}

// ---------------- tensor-core causal flash attention (all tf32 bits) ----------------
__global__ __launch_bounds__(256, 2) void flash_tc(
    const uint32_t* __restrict__ Q, const uint32_t* __restrict__ K,
    const uint32_t* __restrict__ V, uint32_t* __restrict__ O)
{
    extern __shared__ uint32_t smu[];
    uint32_t* Qs = smu;                          // [128][QP]
    uint32_t* Ks = smu + FQ * QP;                // [64][QP]
    uint32_t* Ps = smu + FQ * QP + FK * QP;      // [128][QP]
    uint32_t* Vs = smu + 2 * FQ * QP + FK * QP;  // [64][VP]

    const int tid  = threadIdx.x;
    const int lane = tid & 31;
    const int w    = tid >> 5;
    const int g    = lane >> 2;
    const int tig  = lane & 3;

    const int qtile = blockIdx.x;
    const int h     = blockIdx.y;
    const int b     = blockIdx.z;
    const int kvh   = h >> 2;
    const size_t qtok0 = (size_t)b * T_SEQ + qtile * FQ;

    // Q tile: raw copy (already scaled + tf32)
    {
        const int row = tid >> 4;
        const int c4  = tid & 15;
#pragma unroll
        for (int r = 0; r < 8; r++) {
            int rr = row + r * 16;
            *(uint4*)&Qs[rr * QP + c4 * 4] =
                *(const uint4*)(Q + (qtok0 + rr) * HDIM + h * HD + c4 * 4);
        }
    }

    float m[2], l[2], oacc[8][4];
    m[0] = m[1] = -1e30f; l[0] = l[1] = 0.f;
#pragma unroll
    for (int nt = 0; nt < 8; nt++)
#pragma unroll
        for (int i = 0; i < 4; i++) oacc[nt][i] = 0.f;

    const int ktmax = 2 * qtile + 1;

    for (int kt = 0; kt <= ktmax; kt++) {
        const size_t ktok0 = (size_t)b * T_SEQ + kt * FK;
        __syncthreads();
        {
            const int row = tid >> 4;
            const int c4  = tid & 15;
#pragma unroll
            for (int r = 0; r < 4; r++) {
                int rr = row + r * 16;
                *(uint4*)&Ks[rr * QP + c4 * 4] =
                    *(const uint4*)(K + (ktok0 + rr) * KVDIM + kvh * HD + c4 * 4);
                *(uint4*)&Vs[rr * VP + c4 * 4] =
                    *(const uint4*)(V + (ktok0 + rr) * KVDIM + kvh * HD + c4 * 4);
            }
        }
        __syncthreads();

        float sacc[8][4];
#pragma unroll
        for (int nt = 0; nt < 8; nt++)
#pragma unroll
            for (int i = 0; i < 4; i++) sacc[nt][i] = 0.f;

#pragma unroll
        for (int ks = 0; ks < 8; ks++) {
            uint32_t af[4];
            const uint32_t* qb = &Qs[(w * 16 + g) * QP + ks * 8 + tig];
            af[0] = qb[0];
            af[1] = qb[8 * QP];
            af[2] = qb[4];
            af[3] = qb[8 * QP + 4];
#pragma unroll
            for (int nt = 0; nt < 8; nt++) {
                uint32_t b0 = Ks[(nt * 8 + g) * QP + ks * 8 + tig];
                uint32_t b1 = Ks[(nt * 8 + g) * QP + ks * 8 + tig + 4];
                mma_tf32(sacc[nt], af, b0, b1);
            }
        }

        if (kt >= 2 * qtile) {
#pragma unroll
            for (int nt = 0; nt < 8; nt++)
#pragma unroll
                for (int i = 0; i < 4; i++) {
                    int rowg = qtile * FQ + w * 16 + g + (i >> 1) * 8;
                    int colg = kt * FK + nt * 8 + 2 * tig + (i & 1);
                    if (colg > rowg) sacc[nt][i] = -1e30f;
                }
        }

#pragma unroll
        for (int hh = 0; hh < 2; hh++) {
            float mx = -1e30f;
#pragma unroll
            for (int nt = 0; nt < 8; nt++)
                mx = fmaxf(mx, fmaxf(sacc[nt][2 * hh], sacc[nt][2 * hh + 1]));
            mx = fmaxf(mx, __shfl_xor_sync(0xffffffffu, mx, 1));
            mx = fmaxf(mx, __shfl_xor_sync(0xffffffffu, mx, 2));
            float mn = fmaxf(m[hh], mx);
            float fac = __expf(m[hh] - mn);
            m[hh] = mn;
            float rs = 0.f;
#pragma unroll
            for (int nt = 0; nt < 8; nt++) {
                float p0 = __expf(sacc[nt][2 * hh]     - mn);
                float p1 = __expf(sacc[nt][2 * hh + 1] - mn);
                sacc[nt][2 * hh] = p0; sacc[nt][2 * hh + 1] = p1;
                rs += p0 + p1;
            }
            rs += __shfl_xor_sync(0xffffffffu, rs, 1);
            rs += __shfl_xor_sync(0xffffffffu, rs, 2);
            l[hh] = l[hh] * fac + rs;
#pragma unroll
            for (int nt = 0; nt < 8; nt++) {
                oacc[nt][2 * hh]     *= fac;
                oacc[nt][2 * hh + 1] *= fac;
            }
        }

#pragma unroll
        for (int nt = 0; nt < 8; nt++) {
            uint2 p01, p23;
            p01.x = f2tf(sacc[nt][0]); p01.y = f2tf(sacc[nt][1]);
            p23.x = f2tf(sacc[nt][2]); p23.y = f2tf(sacc[nt][3]);
            *(uint2*)&Ps[(w * 16 + g)     * QP + nt * 8 + 2 * tig] = p01;
            *(uint2*)&Ps[(w * 16 + g + 8) * QP + nt * 8 + 2 * tig] = p23;
        }
        __syncwarp();

#pragma unroll
        for (int ks = 0; ks < 8; ks++) {
            uint32_t pf[4];
            const uint32_t* pb = &Ps[(w * 16 + g) * QP + ks * 8 + tig];
            pf[0] = pb[0];
            pf[1] = pb[8 * QP];
            pf[2] = pb[4];
            pf[3] = pb[8 * QP + 4];
#pragma unroll
            for (int nt = 0; nt < 8; nt++) {
                uint32_t b0 = Vs[(ks * 8 + tig) * VP + nt * 8 + g];
                uint32_t b1 = Vs[(ks * 8 + tig + 4) * VP + nt * 8 + g];
                mma_tf32(oacc[nt], pf, b0, b1);
            }
        }
    }

    float inv0 = 1.0f / l[0], inv1 = 1.0f / l[1];
#pragma unroll
    for (int nt = 0; nt < 8; nt++) {
        size_t row0 = qtok0 + w * 16 + g;
        int col = h * HD + nt * 8 + 2 * tig;
        uint2 u0 = make_uint2(f2tf(oacc[nt][0] * inv0), f2tf(oacc[nt][1] * inv0));
        uint2 u1 = make_uint2(f2tf(oacc[nt][2] * inv1), f2tf(oacc[nt][3] * inv1));
        *(uint2*)&O[row0 * HDIM + col]       = u0;
        *(uint2*)&O[(row0 + 8) * HDIM + col] = u1;
    }
}

// ---------------- launch ----------------
extern "C" void kernel_launch(void* const* d_in, const int* in_sizes, int n_in,
                              void* d_out, int out_size) {
    const float* x  = (const float*)d_in[0];
    const float* wq = (const float*)d_in[1];
    const float* wk = (const float*)d_in[2];
    const float* wv = (const float*)d_in[3];
    const float* wo = (const float*)d_in[4];
    float* out = (float*)d_out;

    uint32_t *xb, *wqb, *wkb, *wvb, *wob, *q, *k, *v, *attn;
    float2* cs;
    cudaGetSymbolAddress((void**)&xb,   g_x);
    cudaGetSymbolAddress((void**)&wqb,  g_wq);
    cudaGetSymbolAddress((void**)&wkb,  g_wk);
    cudaGetSymbolAddress((void**)&wvb,  g_wv);
    cudaGetSymbolAddress((void**)&wob,  g_wo);
    cudaGetSymbolAddress((void**)&q,    g_q);
    cudaGetSymbolAddress((void**)&k,    g_k);
    cudaGetSymbolAddress((void**)&v,    g_v);
    cudaGetSymbolAddress((void**)&attn, g_attn);
    cudaGetSymbolAddress((void**)&cs,   g_cs);

    cudaFuncSetAttribute(gemm_qkv, cudaFuncAttributeMaxDynamicSharedMemorySize, GEMM_SMEM);
    cudaFuncSetAttribute(gemm_wo,  cudaFuncAttributeMaxDynamicSharedMemorySize, GEMM_SMEM);
    cudaFuncSetAttribute(flash_tc, cudaFuncAttributeMaxDynamicSharedMemorySize, FLASH_SMEM);

    cossin_kernel<<<(T_SEQ * 32) / 256, 256>>>(cs);

    auto cvt = [&](const float* src, uint32_t* dst, int n) {
        int n4 = n / 4;
        cvt_tf32_kernel<<<(n4 + 255) / 256, 256>>>((const float4*)src, (uint4*)dst, n4);
    };
    cvt(x,  xb,  NTOK * HDIM);
    cvt(wq, wqb, HDIM * HDIM);
    cvt(wk, wkb, HDIM * KVDIM);
    cvt(wv, wvb, HDIM * KVDIM);
    cvt(wo, wob, HDIM * HDIM);

    gemm_qkv<<<dim3(12, NTOK / BM), 256, GEMM_SMEM>>>(xb, wqb, wkb, wvb, q, k, v, cs);

    flash_tc<<<dim3(T_SEQ / FQ, NH, 2), 256, FLASH_SMEM>>>(q, k, v, attn);

    gemm_wo<<<dim3(HDIM / BN, NTOK / BM), 256, GEMM_SMEM>>>(attn, wob, out);
}